// round 7
// baseline (speedup 1.0000x reference)
#include <cuda_runtime.h>
#include <math.h>
#include <float.h>

// Problem constants: B=8, Z=4, X=32, Y=32, N=4096
#define NPTS   4096
#define NB     8
#define T      512
#define NW     (T / 32)          // 16 warps
#define CHUNK  1024
#define NCH    (NPTS / CHUNK)    // 4 chunks
#define F4PC   (CHUNK * 10 / 4 / T)   // = 5 float4 per thread per tensor per chunk
#define PPT    (CHUNK / T)       // 2 points per thread per chunk
#define RITER  (NPTS / T)        // 8 points per thread in block scans
#define MAXK   16
#define CUT2   4.0f              // sqrt(ss) < 2  <=>  ss < 4  (exact)

// smem: sP4[4096]*16B + sT4[4096]*16B + staging SP/ST (2 * 10240 floats)
#define SMEM_BYTES (NPTS * 16 * 2 + 2 * CHUNK * 10 * 4)

__device__ __forceinline__ float row_angle(float ax, float ay, float az,
                                           float bx, float by, float bz) {
    float na = sqrtf(ax * ax + ay * ay + az * az);
    float nb = sqrtf(bx * bx + by * by + bz * bz);
    float c = (ax * bx + ay * by + az * bz) / (na * nb);
    c = fminf(1.0f, fmaxf(-1.0f, c));
    return (acosf(c) / 3.14159265358979323846f) * 180.0f;
}

__global__ __launch_bounds__(T, 1)
void mol_kernel(const float* __restrict__ pred,
                const float* __restrict__ targ,
                float* __restrict__ out) {
    extern __shared__ float sm[];
    float4* sP4 = (float4*)sm;              // [NPTS] (x,y,z norm, conf|-FLT_MAX)
    float4* sT4 = sP4 + NPTS;               // [NPTS] (tx real|1e30, ty, tz, -)
    float4* SP4 = sT4 + NPTS;               // [CHUNK*10/4] raw pred staging
    float4* ST4 = SP4 + CHUNK * 10 / 4;     // [CHUNK*10/4] raw targ staging
    float*  SP  = (float*)SP4;
    float*  ST  = (float*)ST4;
    float*  smf = sm;                       // scalar view of sP4 for .w stores

    __shared__ float wv[NW];
    __shared__ int wiA[NW];
    __shared__ int sK, sSel, sNTG;
    __shared__ float selp[3];
    __shared__ int   kId[MAXK];
    __shared__ float kRX[MAXK], kRY[MAXK], kRZ[MAXK];
    __shared__ int   sMatch[MAXK], sHit[MAXK];
    __shared__ float sAngA[MAXK];

    const int tid = threadIdx.x;
    const int lane = tid & 31;
    const int warp = tid >> 5;
    const int b = blockIdx.x;

    const float4* gp4 = (const float4*)(pred + (size_t)b * NPTS * 10);
    const float4* gt4 = (const float4*)(targ + (size_t)b * NPTS * 10);
    const int cstride = CHUNK * 10 / 4;     // float4 per chunk = 2560

    // ---- Phase 1: software-pipelined deep-MLP load + parse ----
    float4 rp[2][F4PC], rt[2][F4PC];
    // issue chunk 0 loads (10 back-to-back LDG.128 -> MLP=10)
    #pragma unroll
    for (int j = 0; j < F4PC; j++) rp[0][j] = gp4[tid + j * T];
    #pragma unroll
    for (int j = 0; j < F4PC; j++) rt[0][j] = gt4[tid + j * T];

    int cnt = 0;
    #pragma unroll
    for (int c = 0; c < NCH; c++) {
        int cur = c & 1, nxt = cur ^ 1;
        if (c + 1 < NCH) {   // prefetch next chunk before draining current
            const float4* gpn = gp4 + (c + 1) * cstride;
            const float4* gtn = gt4 + (c + 1) * cstride;
            #pragma unroll
            for (int j = 0; j < F4PC; j++) rp[nxt][j] = gpn[tid + j * T];
            #pragma unroll
            for (int j = 0; j < F4PC; j++) rt[nxt][j] = gtn[tid + j * T];
        }
        #pragma unroll
        for (int j = 0; j < F4PC; j++) SP4[tid + j * T] = rp[cur][j];
        #pragma unroll
        for (int j = 0; j < F4PC; j++) ST4[tid + j * T] = rt[cur][j];
        __syncthreads();
        #pragma unroll
        for (int k = 0; k < PPT; k++) {
            int loc = tid + k * T;
            int n = c * CHUNK + loc;
            float fz = (float)(n >> 10), fx = (float)((n >> 5) & 31), fy = (float)(n & 31);
            const float* p = SP + loc * 10;
            const float* t = ST + loc * 10;
            float pc = p[0];
            // sigmoid(conf)>0.5 <=> raw>0 (exact); /4,/32 exact pow2 mults
            sP4[n] = make_float4((p[1] + fz) * 0.25f,
                                 (p[2] + fx) * 0.03125f,
                                 (p[3] + fy) * 0.03125f,
                                 (pc > 0.0f) ? pc : -FLT_MAX);
            bool act = t[0] > 0.5f;
            cnt += act ? 1 : 0;
            // real coords; inactive -> x sentinel makes every distance test fail
            sT4[n] = make_float4(act ? ((t[1] + fz) * 0.25f) * 25.0f : 1e30f,
                                 ((t[2] + fx) * 0.03125f) * 25.0f,
                                 ((t[3] + fy) * 0.03125f) * 4.0f,
                                 0.0f);
        }
        __syncthreads();
    }

    // active-target count
    #pragma unroll
    for (int o = 16; o; o >>= 1) cnt += __shfl_down_sync(0xffffffffu, cnt, o);
    if (lane == 0) wiA[warp] = cnt;
    if (tid == 0) {
        sK = 0;
        selp[0] = 1e30f; selp[1] = 1e30f; selp[2] = 1e30f;   // round 0: no suppression
    }
    __syncthreads();
    if (tid == 0) {
        int s = 0;
        for (int w = 0; w < NW; w++) s += wiA[w];
        sNTG = s;
    }
    __syncthreads();

    // ---- Phase 2: greedy NMS; suppression of previous pick fused into argmax ----
    for (;;) {
        float c0 = selp[0], c1 = selp[1], c2 = selp[2];
        float bv = -FLT_MAX;
        int bi = 0x7fffffff;
        #pragma unroll
        for (int j = 0; j < RITER; j++) {
            int n = j * T + tid;
            float4 q = sP4[n];
            float v = q.w;
            if (v != -FLT_MAX) {
                float d0 = q.x - c0, d1 = q.y - c1, d2 = q.z - c2;
                float ss = (d0 * d0 + d1 * d1) + d2 * d2;
                if (ss < CUT2) { smf[4 * n + 3] = -FLT_MAX; v = -FLT_MAX; }
            }
            if (v > bv) { bv = v; bi = n; }   // ascending n keeps lowest idx on tie
        }
        #pragma unroll
        for (int o = 16; o; o >>= 1) {
            float v2 = __shfl_down_sync(0xffffffffu, bv, o);
            int i2 = __shfl_down_sync(0xffffffffu, bi, o);
            if (v2 > bv || (v2 == bv && i2 < bi)) { bv = v2; bi = i2; }
        }
        if (lane == 0) { wv[warp] = bv; wiA[warp] = bi; }
        __syncthreads();
        if (warp == 0) {
            float v = (lane < NW) ? wv[lane] : -FLT_MAX;
            int i = (lane < NW) ? wiA[lane] : 0x7fffffff;
            #pragma unroll
            for (int o = 8; o; o >>= 1) {
                float v2 = __shfl_down_sync(0xffffffffu, v, o);
                int i2 = __shfl_down_sync(0xffffffffu, i, o);
                if (v2 > v || (v2 == v && i2 < i)) { v = v2; i = i2; }
            }
            if (lane == 0) {
                if (v == -FLT_MAX || sK >= MAXK) {
                    sSel = -1;
                } else {
                    int K = sK;
                    float4 q = sP4[i];
                    kId[K] = i;
                    kRX[K] = q.x * 25.0f; kRY[K] = q.y * 25.0f; kRZ[K] = q.z * 4.0f;
                    selp[0] = q.x; selp[1] = q.y; selp[2] = q.z;
                    sK = K + 1;
                    sSel = i;
                }
            }
        }
        __syncthreads();
        if (sSel < 0) break;
    }

    // ---- Phase 3: matching, warp-parallel — warp w handles kept points w, w+16 ----
    const int K = sK;
    for (int k = warp; k < K; k += NW) {
        float qx = kRX[k], qy = kRY[k], qz = kRZ[k];
        int best = 0x7fffffff;
        #pragma unroll 4
        for (int e = lane; e < NPTS; e += 32) {
            float4 q = sT4[e];
            float d0 = q.x - qx, d1 = q.y - qy, d2 = q.z - qz;
            float ss = (d0 * d0 + d1 * d1) + d2 * d2;
            if (ss < CUT2 && e < best) best = e;   // sentinel 1e30 auto-fails
        }
        #pragma unroll
        for (int o = 16; o; o >>= 1) {
            int v2 = __shfl_down_sync(0xffffffffu, best, o);
            if (v2 < best) best = v2;
        }
        if (lane == 0) sMatch[k] = best;
    }
    __syncthreads();

    // ---- Phase 4: K parallel angle computations (global reads, L2-hot) ----
    if (tid < K) {
        int mt = sMatch[tid];
        if (mt != 0x7fffffff) {
            const float* p = pred + ((size_t)b * NPTS + kId[tid]) * 10 + 4;
            const float* t = targ + ((size_t)b * NPTS + mt) * 10 + 4;
            float2 pa2 = *(const float2*)p;
            float2 pb2 = *(const float2*)(p + 2);
            float2 pc2 = *(const float2*)(p + 4);
            float2 ta2 = *(const float2*)t;
            float2 tb2 = *(const float2*)(t + 2);
            float2 tc2 = *(const float2*)(t + 4);
            float ax = pa2.x, ay = pa2.y, az = pb2.x;
            float bx = pb2.y, by = pc2.x, bz = pc2.y;
            float cx = ay * bz - az * by;
            float cy = az * bx - ax * bz;
            float cz = ax * by - ay * bx;
            float tax = ta2.x, tay = ta2.y, taz = tb2.x;
            float tbx = tb2.y, tby = tc2.x, tbz = tc2.y;
            float tcx = tay * tbz - taz * tby;
            float tcy = taz * tbx - tax * tbz;
            float tcz = tax * tby - tay * tbx;
            sAngA[tid] = row_angle(ax, ay, az, tax, tay, taz)
                       + row_angle(bx, by, bz, tbx, tby, tbz)
                       + row_angle(cx, cy, cz, tcx, tcy, tcz);
            sHit[tid] = 1;
        } else {
            sAngA[tid] = 0.0f;
            sHit[tid] = 0;
        }
    }
    __syncthreads();

    // ---- Phase 5: deterministic epilogue ----
    if (tid == 0) {
        int tp = 0;
        float ang = 0.0f;
        for (int k = 0; k < K; k++) { tp += sHit[k]; ang += sAngA[k]; }
        float tpf = (float)tp;
        out[b * 3 + 0] = tpf;
        out[b * 3 + 1] = (float)K - tpf;
        out[b * 3 + 2] = (float)sNTG - tpf;
        out[3 * NB + b] = (tp > 0) ? (ang / (3.0f * tpf)) : 0.0f;
    }
}

extern "C" void kernel_launch(void* const* d_in, const int* in_sizes, int n_in,
                              void* d_out, int out_size) {
    const float* pred = (const float*)d_in[0];
    const float* targ = (const float*)d_in[1];
    float* out = (float*)d_out;
    cudaFuncSetAttribute(mol_kernel, cudaFuncAttributeMaxDynamicSharedMemorySize,
                         SMEM_BYTES);
    mol_kernel<<<NB, T, SMEM_BYTES>>>(pred, targ, out);
}

// round 8
// speedup vs baseline: 1.3851x; 1.3851x over previous
#include <cuda_runtime.h>
#include <math.h>
#include <float.h>

// Problem constants (from reference): B=8, Z=4, X=32, Y=32, N=4096
#define NPTS   4096
#define NB     8
#define THREADS 512
#define NWARP  (THREADS / 32)
#define NITER  (NPTS / THREADS)   // 8
#define MAXKEEP 128
#define CUT2   4.0f               // sqrt(ss) < 2  <=>  ss < 4 (exact)

// Dynamic smem: 8 arrays of NPTS floats + warp scratch + kept arrays
#define SMEM_BYTES ((8 * NPTS + 2 * NWARP + 4 * MAXKEEP) * 4)

__device__ __forceinline__ float row_angle(float ax, float ay, float az,
                                           float bx, float by, float bz) {
    float na = sqrtf(ax * ax + ay * ay + az * az);
    float nb = sqrtf(bx * bx + by * by + bz * bz);
    float c = (ax * bx + ay * by + az * bz) / (na * nb);
    c = fminf(1.0f, fmaxf(-1.0f, c));
    return (acosf(c) / 3.14159265358979323846f) * 180.0f;
}

__global__ __launch_bounds__(THREADS, 1)
void mol_kernel(const float* __restrict__ pred,
                const float* __restrict__ targ,
                float* __restrict__ out) {
    extern __shared__ float sm[];
    float* s_conf = sm;                 // [NPTS] pred conf (raw, -FLT_MAX = inactive)
    float* s_p0 = s_conf + NPTS;        // [NPTS] pred pos normalized
    float* s_p1 = s_p0 + NPTS;
    float* s_p2 = s_p1 + NPTS;
    float* s_t0 = s_p2 + NPTS;          // [NPTS] target pos in REAL coords
    float* s_t1 = s_t0 + NPTS;
    float* s_t2 = s_t1 + NPTS;
    float* s_tc = s_t2 + NPTS;          // [NPTS] target conf
    float* wv = s_tc + NPTS;            // [NWARP]
    int* wi = (int*)(wv + NWARP);       // [NWARP]
    float* kx = (float*)(wi + NWARP);   // kept point normalized coords
    float* ky = kx + MAXKEEP;
    float* kz = ky + MAXKEEP;
    int* kid = (int*)(kz + MAXKEEP);    // kept original indices

    __shared__ int sK, sSel, sTP, sNTG;
    __shared__ float sAng;
    __shared__ float selp[3];

    const int tid = threadIdx.x;
    const int lane = tid & 31;
    const int warp = tid >> 5;
    const int b = blockIdx.x;
    const float* P = pred + (long long)b * NPTS * 10;
    const float* T = targ + (long long)b * NPTS * 10;

    // ---- Phase 1: vectorized, fully-unrolled load (high MLP) ----
    #pragma unroll
    for (int j = 0; j < NITER; j++) {
        int n = tid + j * THREADS;
        const float* p = P + n * 10;
        const float* t = T + n * 10;
        // 40-byte pitch is 8-byte aligned for every n -> float2 loads legal
        float2 p01 = *(const float2*)p;
        float2 p23 = *(const float2*)(p + 2);
        float2 t01 = *(const float2*)t;
        float2 t23 = *(const float2*)(t + 2);
        float z = (float)(n >> 10), x = (float)((n >> 5) & 31), y = (float)(n & 31);
        // sigmoid(c) > 0.5  <=>  c > 0  (exact)
        s_conf[n] = (p01.x > 0.0f) ? p01.x : -FLT_MAX;
        // normalized pos: (offset + cell)/ZXY ; /4 and /32 are exact pow2 mults
        s_p0[n] = (p01.y + z) * 0.25f;
        s_p1[n] = (p23.x + x) * 0.03125f;
        s_p2[n] = (p23.y + y) * 0.03125f;
        // target: real coords = normalized * REAL_SIZE(25,25,4)
        s_tc[n] = t01.x;
        s_t0[n] = ((t01.y + z) * 0.25f) * 25.0f;
        s_t1[n] = ((t23.x + x) * 0.03125f) * 25.0f;
        s_t2[n] = ((t23.y + y) * 0.03125f) * 4.0f;
    }
    if (tid == 0) { sK = 0; sTP = 0; sAng = 0.0f; }
    __syncthreads();

    // ---- Phase 2: round-based greedy NMS (== converged iterative suppression) ----
    for (;;) {
        // block argmax over remaining confidence (tie -> lowest index)
        float bv = -FLT_MAX;
        int bi = 0x7fffffff;
        #pragma unroll
        for (int j = 0; j < NITER; j++) {
            int n = tid + j * THREADS;
            float v = s_conf[n];
            if (v > bv) { bv = v; bi = n; }   // ascending n => ties keep lowest idx
        }
        #pragma unroll
        for (int o = 16; o; o >>= 1) {
            float v2 = __shfl_down_sync(0xffffffffu, bv, o);
            int i2 = __shfl_down_sync(0xffffffffu, bi, o);
            if (v2 > bv || (v2 == bv && i2 < bi)) { bv = v2; bi = i2; }
        }
        if (lane == 0) { wv[warp] = bv; wi[warp] = bi; }
        __syncthreads();
        if (warp == 0) {
            float v = (lane < NWARP) ? wv[lane] : -FLT_MAX;
            int i = (lane < NWARP) ? wi[lane] : 0x7fffffff;
            #pragma unroll
            for (int o = 8; o; o >>= 1) {
                float v2 = __shfl_down_sync(0xffffffffu, v, o);
                int i2 = __shfl_down_sync(0xffffffffu, i, o);
                if (v2 > v || (v2 == v && i2 < i)) { v = v2; i = i2; }
            }
            if (lane == 0) {
                if (v == -FLT_MAX || sK >= MAXKEEP) {
                    sSel = -1;
                } else {
                    sSel = i;
                    int K = sK;
                    kx[K] = s_p0[i]; ky[K] = s_p1[i]; kz[K] = s_p2[i]; kid[K] = i;
                    selp[0] = s_p0[i]; selp[1] = s_p1[i]; selp[2] = s_p2[i];
                    sK = K + 1;
                }
            }
        }
        __syncthreads();
        if (sSel < 0) break;
        // suppress everything within CUT of selected (includes itself, d=0)
        float c0 = selp[0], c1 = selp[1], c2 = selp[2];
        #pragma unroll
        for (int j = 0; j < NITER; j++) {
            int n = tid + j * THREADS;
            if (s_conf[n] != -FLT_MAX) {
                float d0 = s_p0[n] - c0, d1 = s_p1[n] - c1, d2 = s_p2[n] - c2;
                float ss = (d0 * d0 + d1 * d1) + d2 * d2;
                if (ss < CUT2) s_conf[n] = -FLT_MAX;
            }
        }
        __syncthreads();
    }

    // ---- Phase 3a: count active targets ----
    {
        int cnt = 0;
        #pragma unroll
        for (int j = 0; j < NITER; j++) {
            int n = tid + j * THREADS;
            cnt += (s_tc[n] > 0.5f) ? 1 : 0;
        }
        #pragma unroll
        for (int o = 16; o; o >>= 1) cnt += __shfl_down_sync(0xffffffffu, cnt, o);
        if (lane == 0) wi[warp] = cnt;
        __syncthreads();
        if (tid == 0) {
            int s = 0;
            for (int w = 0; w < NWARP; w++) s += wi[w];
            sNTG = s;
        }
        __syncthreads();
    }

    // ---- Phase 3b: per kept pred, find first in-range active target; angles ----
    const int K = sK;
    for (int k = 0; k < K; k++) {
        float q0 = kx[k] * 25.0f, q1 = ky[k] * 25.0f, q2 = kz[k] * 4.0f;
        int best = 0x7fffffff;
        #pragma unroll
        for (int j = 0; j < NITER; j++) {
            int t = tid + j * THREADS;
            if (s_tc[t] > 0.5f) {
                float d0 = s_t0[t] - q0, d1 = s_t1[t] - q1, d2 = s_t2[t] - q2;
                float ss = (d0 * d0 + d1 * d1) + d2 * d2;
                if (ss < CUT2 && t < best) best = t;
            }
        }
        #pragma unroll
        for (int o = 16; o; o >>= 1) {
            int v2 = __shfl_down_sync(0xffffffffu, best, o);
            if (v2 < best) best = v2;
        }
        if (lane == 0) wi[warp] = best;
        __syncthreads();
        if (tid == 0) {
            int bmin = 0x7fffffff;
            for (int w = 0; w < NWARP; w++) if (wi[w] < bmin) bmin = wi[w];
            if (bmin != 0x7fffffff) {
                sTP += 1;
                int i = kid[k];
                const float* p = P + (long long)i * 10;
                const float* t = T + (long long)bmin * 10;
                float ax = p[4], ay = p[5], az = p[6];
                float bx = p[7], by = p[8], bz = p[9];
                float cx = ay * bz - az * by;
                float cy = az * bx - ax * bz;
                float cz = ax * by - ay * bx;
                float tax = t[4], tay = t[5], taz = t[6];
                float tbx = t[7], tby = t[8], tbz = t[9];
                float tcx = tay * tbz - taz * tby;
                float tcy = taz * tbx - tax * tbz;
                float tcz = tax * tby - tay * tbx;
                sAng += row_angle(ax, ay, az, tax, tay, taz)
                      + row_angle(bx, by, bz, tbx, tby, tbz)
                      + row_angle(cx, cy, cz, tcx, tcy, tcz);
            }
        }
        __syncthreads();
    }

    // ---- Phase 4: write outputs ----
    if (tid == 0) {
        float tp = (float)sTP;
        out[b * 3 + 0] = tp;
        out[b * 3 + 1] = (float)K - tp;
        out[b * 3 + 2] = (float)sNTG - tp;
        out[3 * NB + b] = (sTP > 0) ? (sAng / (3.0f * tp)) : 0.0f;
    }
}

extern "C" void kernel_launch(void* const* d_in, const int* in_sizes, int n_in,
                              void* d_out, int out_size) {
    const float* pred = (const float*)d_in[0];
    const float* targ = (const float*)d_in[1];
    float* out = (float*)d_out;
    cudaFuncSetAttribute(mol_kernel, cudaFuncAttributeMaxDynamicSharedMemorySize,
                         SMEM_BYTES);
    mol_kernel<<<NB, THREADS, SMEM_BYTES>>>(pred, targ, out);
}